// round 4
// baseline (speedup 1.0000x reference)
#include <cuda_runtime.h>
#include <cstddef>

#define HID   128
#define NMAX  50000
#define EMAX  800000
#define XPAD  68        // padded row stride of transposed X tile (floats)

// ---- device-global scratch (sanctioned alloc-free mechanism) ----
__device__ float g_H1[(size_t)NMAX * HID];       // relu(nf @ W1 + b1)
__device__ float g_pooled[(size_t)NMAX * HID];   // segment-sum result
__device__ int   g_cnt[NMAX];                    // per-node edge count (self-cleaned by pool)
__device__ int   g_off[NMAX];                    // CSR offsets
__device__ int   g_cur[NMAX];                    // fill cursors
__device__ int2  g_pedge[EMAX];                  // (src, norm-bits) reordered by tgt

// ---------------------------------------------------------------------------
// GEMM: Y = relu(X @ W + b) [+ res].  X:[nrows,128], W:[128,128] row-major.
// 256 threads, 64-row M-tile, full 128-col N. Packed fp32 FFMA2 with ROW
// pairing: acc[p][c] = (row r0+2p, row r0+2p+1) at col c0+c. Row pairs come
// free from LDS of the transposed X tile; only w needs mov.b64 {w,w}.
// ---------------------------------------------------------------------------
template <bool RESIDUAL>
__global__ __launch_bounds__(256) void gemm_relu_kernel(
    const float* __restrict__ X, const float* __restrict__ W,
    const float* __restrict__ b, const float* __restrict__ res,
    float* __restrict__ Y, int nrows)
{
    extern __shared__ float smem[];
    float* ws  = smem;                // [128][128]  64KB
    float* xst = smem + HID * HID;    // [128][XPAD] (transposed tile)

    const int tid  = threadIdx.x;
    const int row0 = blockIdx.x * 64;

    #pragma unroll
    for (int i = tid; i < HID * HID; i += 256) ws[i] = W[i];

    #pragma unroll
    for (int i = tid; i < 64 * HID; i += 256) {
        int r = i >> 7, k = i & 127;
        int gr = row0 + r;
        xst[k * XPAD + r] = (gr < nrows) ? X[(size_t)gr * HID + k] : 0.f;
    }
    __syncthreads();

    const int cg = tid & 31;
    const int rg = tid >> 5;
    const int c0 = cg << 2;
    const int r0 = rg << 3;

    unsigned long long acc[4][4];
    #pragma unroll
    for (int p = 0; p < 4; p++)
        #pragma unroll
        for (int c = 0; c < 4; c++) acc[p][c] = 0ull;

    #pragma unroll 4
    for (int k = 0; k < HID; k++) {
        ulonglong2 xa = *(const ulonglong2*)&xst[k * XPAD + r0];
        ulonglong2 xb = *(const ulonglong2*)&xst[k * XPAD + r0 + 4];
        unsigned long long xp[4] = {xa.x, xa.y, xb.x, xb.y};

        float4 wv = *(const float4*)&ws[k * HID + c0];
        unsigned long long wd[4];
        asm("mov.b64 %0, {%1, %1};" : "=l"(wd[0]) : "f"(wv.x));
        asm("mov.b64 %0, {%1, %1};" : "=l"(wd[1]) : "f"(wv.y));
        asm("mov.b64 %0, {%1, %1};" : "=l"(wd[2]) : "f"(wv.z));
        asm("mov.b64 %0, {%1, %1};" : "=l"(wd[3]) : "f"(wv.w));

        #pragma unroll
        for (int p = 0; p < 4; p++)
            #pragma unroll
            for (int c = 0; c < 4; c++)
                asm("fma.rn.f32x2 %0, %1, %2, %0;"
                    : "+l"(acc[p][c]) : "l"(xp[p]), "l"(wd[c]));
    }

    float4 bias = *(const float4*)&b[c0];
    #pragma unroll
    for (int p = 0; p < 4; p++) {
        float lo[4], hi[4];
        #pragma unroll
        for (int c = 0; c < 4; c++)
            asm("mov.b64 {%0, %1}, %2;" : "=f"(lo[c]), "=f"(hi[c]) : "l"(acc[p][c]));

        int rowA = row0 + r0 + 2 * p;
        int rowB = rowA + 1;
        if (rowA < nrows) {
            float4 o;
            o.x = fmaxf(lo[0] + bias.x, 0.f);
            o.y = fmaxf(lo[1] + bias.y, 0.f);
            o.z = fmaxf(lo[2] + bias.z, 0.f);
            o.w = fmaxf(lo[3] + bias.w, 0.f);
            if (RESIDUAL) {
                float4 rr = *(const float4*)&res[(size_t)rowA * HID + c0];
                o.x += rr.x; o.y += rr.y; o.z += rr.z; o.w += rr.w;
            }
            *(float4*)&Y[(size_t)rowA * HID + c0] = o;
        }
        if (rowB < nrows) {
            float4 o;
            o.x = fmaxf(hi[0] + bias.x, 0.f);
            o.y = fmaxf(hi[1] + bias.y, 0.f);
            o.z = fmaxf(hi[2] + bias.z, 0.f);
            o.w = fmaxf(hi[3] + bias.w, 0.f);
            if (RESIDUAL) {
                float4 rr = *(const float4*)&res[(size_t)rowB * HID + c0];
                o.x += rr.x; o.y += rr.y; o.z += rr.z; o.w += rr.w;
            }
            *(float4*)&Y[(size_t)rowB * HID + c0] = o;
        }
    }
}

// ---------------------------------------------------------------------------
// CSR build (g_cnt is zero on entry: BSS at load, self-cleaned by pool after)
// ---------------------------------------------------------------------------
__global__ void hist_kernel(const int* __restrict__ tgt, int nedges)
{
    int e = blockIdx.x * blockDim.x + threadIdx.x;
    if (e < nedges) atomicAdd(&g_cnt[tgt[e]], 1);
}

// Single-block exclusive scan of g_cnt -> g_off / g_cur. 1024 threads, each
// owns a contiguous chunk of nodes; warp-shfl scan + smem for warp sums.
__global__ __launch_bounds__(1024) void scan_offsets_kernel(int nnodes)
{
    __shared__ int warpsum[32];
    const int t = threadIdx.x;
    const int per = (nnodes + 1023) >> 10;
    const int begin = t * per;
    const int end = (begin + per < nnodes) ? begin + per : nnodes;

    int local = 0;
    for (int n = begin; n < end; n++) local += g_cnt[n];

    const int lane = t & 31, wid = t >> 5;
    int v = local;
    #pragma unroll
    for (int d = 1; d < 32; d <<= 1) {
        int u = __shfl_up_sync(0xffffffffu, v, d);
        if (lane >= d) v += u;
    }
    if (lane == 31) warpsum[wid] = v;
    __syncthreads();
    if (wid == 0) {
        int w = warpsum[lane];
        #pragma unroll
        for (int d = 1; d < 32; d <<= 1) {
            int u = __shfl_up_sync(0xffffffffu, w, d);
            if (lane >= d) w += u;
        }
        warpsum[lane] = w;
    }
    __syncthreads();

    int excl = v - local + ((wid > 0) ? warpsum[wid - 1] : 0);
    for (int n = begin; n < end; n++) {
        g_off[n] = excl;
        g_cur[n] = excl;
        excl += g_cnt[n];
    }
}

__global__ void fill_kernel(const int* __restrict__ src,
                            const int* __restrict__ tgt,
                            const float* __restrict__ norm, int nedges)
{
    int e = blockIdx.x * blockDim.x + threadIdx.x;
    if (e >= nedges) return;
    int t = tgt[e];
    int pos = atomicAdd(&g_cur[t], 1);
    g_pedge[pos] = make_int2(src[e], __float_as_int(norm[e]));
}

// ---------------------------------------------------------------------------
// Pool: warp per node. pooled[n] = sum_{edges into n} norm * H1[src].
// Lane l owns floats [l*4, l*4+4). Self-cleans g_cnt for the next replay.
// ---------------------------------------------------------------------------
__global__ __launch_bounds__(256) void pool_kernel(int nnodes)
{
    int n = blockIdx.x * 8 + (threadIdx.x >> 5);
    if (n >= nnodes) return;
    int lane = threadIdx.x & 31;

    int off = g_off[n];
    int cnt = g_cnt[n];
    __syncwarp();
    if (lane == 0) g_cnt[n] = 0;   // reset for next graph replay

    float4 acc = make_float4(0.f, 0.f, 0.f, 0.f);
    if (cnt > 0) {
        int2  p  = g_pedge[off];
        float nm = __int_as_float(p.y);
        float4 v = *(const float4*)&g_H1[(size_t)p.x * HID + lane * 4];
        for (int j = 1; j < cnt; j++) {
            int2  p2  = g_pedge[off + j];
            float nm2 = __int_as_float(p2.y);
            float4 v2 = *(const float4*)&g_H1[(size_t)p2.x * HID + lane * 4];
            acc.x = fmaf(nm, v.x, acc.x);
            acc.y = fmaf(nm, v.y, acc.y);
            acc.z = fmaf(nm, v.z, acc.z);
            acc.w = fmaf(nm, v.w, acc.w);
            v = v2; nm = nm2;
        }
        acc.x = fmaf(nm, v.x, acc.x);
        acc.y = fmaf(nm, v.y, acc.y);
        acc.z = fmaf(nm, v.z, acc.z);
        acc.w = fmaf(nm, v.w, acc.w);
    }
    *(float4*)&g_pooled[(size_t)n * HID + lane * 4] = acc;
}

// ---------------------------------------------------------------------------
// Launch: fork CSR build onto a side stream so it overlaps GEMM1.
// (Event fork/join is the capture-legal cross-stream pattern.)
// ---------------------------------------------------------------------------
extern "C" void kernel_launch(void* const* d_in, const int* in_sizes, int n_in,
                              void* d_out, int out_size)
{
    const float* nf   = (const float*)d_in[0];
    const int*   src  = (const int*)d_in[1];
    const int*   tgt  = (const int*)d_in[2];
    const float* norm = (const float*)d_in[3];
    const float* W1   = (const float*)d_in[4];
    const float* b1   = (const float*)d_in[5];
    const float* W2   = (const float*)d_in[6];
    const float* b2   = (const float*)d_in[7];
    float*       out  = (float*)d_out;

    const int nnodes = in_sizes[0] / HID;
    const int nedges = in_sizes[1];

    const size_t smem = (size_t)(HID * HID + HID * XPAD) * sizeof(float);
    cudaFuncSetAttribute(gemm_relu_kernel<false>,
                         cudaFuncAttributeMaxDynamicSharedMemorySize, (int)smem);
    cudaFuncSetAttribute(gemm_relu_kernel<true>,
                         cudaFuncAttributeMaxDynamicSharedMemorySize, (int)smem);

    float *H1 = nullptr, *pooled = nullptr;
    cudaGetSymbolAddress((void**)&H1, g_H1);
    cudaGetSymbolAddress((void**)&pooled, g_pooled);

    const int gblocks = (nnodes + 63) / 64;

    // Side stream + events (host-side objects only; kernel_launch is called
    // twice total, so the small host leak is irrelevant and keeps the
    // captured-resource lifetime safe).
    cudaStream_t s2;
    cudaStreamCreateWithFlags(&s2, cudaStreamNonBlocking);
    cudaEvent_t e1, e2;
    cudaEventCreateWithFlags(&e1, cudaEventDisableTiming);
    cudaEventCreateWithFlags(&e2, cudaEventDisableTiming);

    // Fork point: CSR chain depends only on prior state, not on GEMM1.
    cudaEventRecord(e1, 0);

    // Main stream: GEMM1  H1 = relu(nf @ W1 + b1)
    gemm_relu_kernel<false><<<gblocks, 256, smem>>>(nf, W1, b1, nullptr, H1, nnodes);

    // Side stream: CSR build (hist -> scan -> fill), overlapped with GEMM1
    cudaStreamWaitEvent(s2, e1, 0);
    hist_kernel<<<(nedges + 255) / 256, 256, 0, s2>>>(tgt, nedges);
    scan_offsets_kernel<<<1, 1024, 0, s2>>>(nnodes);
    fill_kernel<<<(nedges + 255) / 256, 256, 0, s2>>>(src, tgt, norm, nedges);
    cudaEventRecord(e2, s2);

    // Join, then pool + GEMM2 on the main stream
    cudaStreamWaitEvent(0, e2, 0);
    pool_kernel<<<(nnodes + 7) / 8, 256>>>(nnodes);
    gemm_relu_kernel<true><<<gblocks, 256, smem>>>(pooled, W2, b2, nf, out, nnodes);
}